// round 12
// baseline (speedup 1.0000x reference)
#include <cuda_runtime.h>
#include <cuda_bf16.h>
#include <cstdint>

#define N_MAX   100000
#define E_MAX   3200000
#define NH      4
#define INDIM   128
#define REL     50
#define PD      16

// ---------------- scratch (device globals; no allocation allowed) -------------
__device__ __align__(16) float  d_w[3 * REL * NH];   // exp(leaky(rel_emb@W_pred))
__device__ __align__(16) float4 d_h0[N_MAX];         // MLP output (N,4)
__device__ float d_h1s[N_MAX];
__device__ float d_h2s[N_MAX];
__device__ unsigned d_deg[N_MAX];                    // in-degree
__device__ unsigned d_off[N_MAX + 1];                // CSR offsets
__device__ unsigned d_cur[N_MAX];                    // scatter cursors
__device__ unsigned d_edges[E_MAX];                  // packed (type<<17 | src)
__device__ unsigned d_bsum[128];                     // scan block sums

// ---------------- init: attention tables + zero degree --------------------------
__global__ void k_init(const float* __restrict__ rel_emb,
                       const float* __restrict__ W_pred, int n) {
    int gt = blockIdx.x * blockDim.x + threadIdx.x;
    if (gt < 3 * REL * NH) {
        int l = gt / (REL * NH);
        int r = gt - l * (REL * NH);
        int t = r >> 2, h = r & 3;
        float acc = 0.f;
#pragma unroll
        for (int p = 0; p < PD; ++p)
            acc += rel_emb[t * PD + p] * W_pred[l * PD * NH + p * NH + h];
        float e = acc > 0.f ? acc : 0.2f * acc;
        d_w[gt] = expf(e);
    }
    int stride = gridDim.x * blockDim.x;
    for (int i = gt; i < n; i += stride) d_deg[i] = 0u;
}

// ---------------- degree histogram ----------------------------------------------
__global__ void k_hist(const int* __restrict__ dst, int e) {
    int i = blockIdx.x * blockDim.x + threadIdx.x;
    if (i < e) atomicAdd(&d_deg[dst[i]], 1u);
}

// ---------------- 3-kernel exclusive scan over degrees --------------------------
__global__ void k_scanA(int n) {          // per-block sums (block=1024)
    __shared__ unsigned s[1024];
    int idx = blockIdx.x * 1024 + threadIdx.x;
    s[threadIdx.x] = (idx < n) ? d_deg[idx] : 0u;
    __syncthreads();
#pragma unroll
    for (int o = 512; o; o >>= 1) {
        if (threadIdx.x < o) s[threadIdx.x] += s[threadIdx.x + o];
        __syncthreads();
    }
    if (threadIdx.x == 0) d_bsum[blockIdx.x] = s[0];
}
__global__ void k_scanB(int nblk) {       // exclusive scan of block sums (1 block)
    __shared__ unsigned s[128];
    unsigned v = (threadIdx.x < nblk) ? d_bsum[threadIdx.x] : 0u;
    s[threadIdx.x] = v;
    __syncthreads();
#pragma unroll
    for (int o = 1; o < 128; o <<= 1) {
        unsigned t = (threadIdx.x >= o) ? s[threadIdx.x - o] : 0u;
        __syncthreads();
        s[threadIdx.x] += t;
        __syncthreads();
    }
    d_bsum[threadIdx.x] = s[threadIdx.x] - v;   // exclusive
}
__global__ void k_scanC(int n) {          // per-block exclusive scan + base
    __shared__ unsigned s[1024];
    int idx = blockIdx.x * 1024 + threadIdx.x;
    unsigned x = (idx < n) ? d_deg[idx] : 0u;
    s[threadIdx.x] = x;
    __syncthreads();
#pragma unroll
    for (int o = 1; o < 1024; o <<= 1) {
        unsigned t = (threadIdx.x >= o) ? s[threadIdx.x - o] : 0u;
        __syncthreads();
        s[threadIdx.x] += t;
        __syncthreads();
    }
    unsigned base = d_bsum[blockIdx.x];
    if (idx < n) {
        unsigned off = base + s[threadIdx.x] - x;   // exclusive
        d_off[idx] = off;
        d_cur[idx] = off;
        if (idx == n - 1) d_off[n] = base + s[threadIdx.x];
    }
}

// ---------------- scatter edges into CSR (packed type|src) ----------------------
__global__ void k_scatter(const int* __restrict__ et, const int* __restrict__ src,
                          const int* __restrict__ dst, int e) {
    int i = blockIdx.x * blockDim.x + threadIdx.x;
    if (i >= e) return;
    unsigned pos = atomicAdd(&d_cur[dst[i]], 1u);
    d_edges[pos] = ((unsigned)et[i] << 17) | (unsigned)src[i];
}

// ================= HMMA (mma.sync) split-bf16 MLP ==============================
#define LDP    40
#define MATB   (128 * LDP * 2)
#define OFF_AH 0
#define OFF_AL MATB
#define OFF_BH (2 * MATB)
#define OFF_BL (3 * MATB)
#define OFF_B1 (4 * MATB)
#define OFF_W2 (OFF_B1 + 512)
#define SM_TOT (OFF_W2 + 512)

__device__ __forceinline__ uint32_t smem_u32(const void* p) {
    uint32_t a;
    asm("{ .reg .u64 t; cvta.to.shared.u64 t, %1; cvt.u32.u64 %0, t; }"
        : "=r"(a) : "l"(p));
    return a;
}
__device__ __forceinline__ uint32_t pack_bf2(__nv_bfloat16 lo, __nv_bfloat16 hi) {
    return (uint32_t)__bfloat16_as_ushort(lo) |
           ((uint32_t)__bfloat16_as_ushort(hi) << 16);
}
#define LDSM_X4(R0, R1, R2, R3, ADDR)                                         \
    asm volatile("ldmatrix.sync.aligned.m8n8.x4.shared.b16 {%0,%1,%2,%3}, [%4];" \
                 : "=r"(R0), "=r"(R1), "=r"(R2), "=r"(R3) : "r"(ADDR))

__device__ __forceinline__ void mma_bf16(float* d, const uint32_t* a,
                                         const uint32_t* b) {
    asm volatile(
        "mma.sync.aligned.m16n8k16.row.col.f32.bf16.bf16.f32 "
        "{%0,%1,%2,%3}, {%4,%5,%6,%7}, {%8,%9}, {%0,%1,%2,%3};"
        : "+f"(d[0]), "+f"(d[1]), "+f"(d[2]), "+f"(d[3])
        : "r"(a[0]), "r"(a[1]), "r"(a[2]), "r"(a[3]), "r"(b[0]), "r"(b[1]));
}

__global__ void __launch_bounds__(256) k_mlp_mma(
    const float* __restrict__ inputs, const float* __restrict__ W1,
    const float* __restrict__ b1, const float* __restrict__ W2,
    const float* __restrict__ b2, int n) {
    __shared__ __align__(16) char sm[SM_TOT];
    const int tid = threadIdx.x;
    const int lane = tid & 31, wid = tid >> 5;
    const int mw = wid & 3, nw = wid >> 2;
    const int xh = blockIdx.x;
    const int n0 = blockIdx.y * 128;

    float* b1s = (float*)(sm + OFF_B1);
    float* w2s = (float*)(sm + OFF_W2);
    if (tid < 128) {
        b1s[tid] = b1[xh * 128 + tid];
        w2s[tid] = W2[xh * 128 + tid];
    }

    float acc[2][8][4];
#pragma unroll
    for (int m = 0; m < 2; ++m)
#pragma unroll
        for (int t = 0; t < 8; ++t)
#pragma unroll
            for (int r = 0; r < 4; ++r) acc[m][t][r] = 0.f;

    const uint32_t sb = smem_u32(sm);
    const int rowA = mw * 32 + (lane & 15);
    const int kA = (lane >> 4) * 8;
    uint32_t aof[2];
#pragma unroll
    for (int m = 0; m < 2; ++m)
        aof[m] = sb + OFF_AH + (uint32_t)(((rowA + m * 16) * LDP + kA) * 2);
    const int colB = nw * 64 + (lane >> 4) * 8 + (lane & 7);
    const int kB = ((lane >> 3) & 1) * 8;
    uint32_t bof[4];
#pragma unroll
    for (int t = 0; t < 4; ++t)
        bof[t] = sb + OFF_BH + (uint32_t)(((colB + t * 16) * LDP + kB) * 2);

    const int sr = tid >> 1;
    const int skb = (tid & 1) * 16;

    for (int kc = 0; kc < 4; ++kc) {
        {
            int node = n0 + sr;
            const float* p = inputs + (size_t)node * INDIM + kc * 32 + skb;
            uint32_t* ah = (uint32_t*)(sm + OFF_AH + (sr * LDP + skb) * 2);
            uint32_t* al = (uint32_t*)(sm + OFF_AL + (sr * LDP + skb) * 2);
            bool ok = node < n;
#pragma unroll
            for (int j = 0; j < 16; j += 4) {
                float4 v = ok ? *(const float4*)(p + j)
                              : make_float4(0.f, 0.f, 0.f, 0.f);
                __nv_bfloat16 hx = __float2bfloat16(v.x);
                __nv_bfloat16 hy = __float2bfloat16(v.y);
                __nv_bfloat16 hz = __float2bfloat16(v.z);
                __nv_bfloat16 hw = __float2bfloat16(v.w);
                ah[j / 2]     = pack_bf2(hx, hy);
                ah[j / 2 + 1] = pack_bf2(hz, hw);
                al[j / 2] = pack_bf2(__float2bfloat16(v.x - __bfloat162float(hx)),
                                     __float2bfloat16(v.y - __bfloat162float(hy)));
                al[j / 2 + 1] =
                    pack_bf2(__float2bfloat16(v.z - __bfloat162float(hz)),
                             __float2bfloat16(v.w - __bfloat162float(hw)));
            }
        }
        {
            const float* q =
                W1 + (size_t)(xh * 128 + sr) * INDIM + kc * 32 + skb;
            uint32_t* bh = (uint32_t*)(sm + OFF_BH + (sr * LDP + skb) * 2);
            uint32_t* bl = (uint32_t*)(sm + OFF_BL + (sr * LDP + skb) * 2);
#pragma unroll
            for (int j = 0; j < 16; j += 4) {
                float4 v = *(const float4*)(q + j);
                __nv_bfloat16 hx = __float2bfloat16(v.x);
                __nv_bfloat16 hy = __float2bfloat16(v.y);
                __nv_bfloat16 hz = __float2bfloat16(v.z);
                __nv_bfloat16 hw = __float2bfloat16(v.w);
                bh[j / 2]     = pack_bf2(hx, hy);
                bh[j / 2 + 1] = pack_bf2(hz, hw);
                bl[j / 2] = pack_bf2(__float2bfloat16(v.x - __bfloat162float(hx)),
                                     __float2bfloat16(v.y - __bfloat162float(hy)));
                bl[j / 2 + 1] =
                    pack_bf2(__float2bfloat16(v.z - __bfloat162float(hz)),
                             __float2bfloat16(v.w - __bfloat162float(hw)));
            }
        }
        __syncthreads();

#pragma unroll
        for (int pass = 0; pass < 3; ++pass) {
            uint32_t ab = (pass == 1) ? (uint32_t)MATB : 0u;
            uint32_t bb = (pass == 2) ? (uint32_t)MATB : 0u;
#pragma unroll
            for (int ks = 0; ks < 2; ++ks) {
                uint32_t a[2][4], b[8][2];
                LDSM_X4(a[0][0], a[0][1], a[0][2], a[0][3],
                        aof[0] + ab + ks * 32);
                LDSM_X4(a[1][0], a[1][1], a[1][2], a[1][3],
                        aof[1] + ab + ks * 32);
#pragma unroll
                for (int t = 0; t < 4; ++t) {
                    uint32_t r0, r1, r2, r3;
                    LDSM_X4(r0, r1, r2, r3, bof[t] + bb + ks * 32);
                    b[2 * t][0] = r0; b[2 * t][1] = r1;
                    b[2 * t + 1][0] = r2; b[2 * t + 1][1] = r3;
                }
#pragma unroll
                for (int m = 0; m < 2; ++m)
#pragma unroll
                    for (int t = 0; t < 8; ++t) mma_bf16(acc[m][t], a[m], b[t]);
            }
        }
        __syncthreads();
    }

    float rs[2][2] = {{0.f, 0.f}, {0.f, 0.f}};
#pragma unroll
    for (int t = 0; t < 8; ++t) {
        int c = nw * 64 + t * 8 + (lane & 3) * 2;
        float bb0 = b1s[c], bb1 = b1s[c + 1];
        float ww0 = w2s[c], ww1 = w2s[c + 1];
#pragma unroll
        for (int m = 0; m < 2; ++m) {
            float v;
            v = acc[m][t][0] + bb0; v = v > 0.f ? v : 0.f; rs[m][0] += v * ww0;
            v = acc[m][t][1] + bb1; v = v > 0.f ? v : 0.f; rs[m][0] += v * ww1;
            v = acc[m][t][2] + bb0; v = v > 0.f ? v : 0.f; rs[m][1] += v * ww0;
            v = acc[m][t][3] + bb1; v = v > 0.f ? v : 0.f; rs[m][1] += v * ww1;
        }
    }
#pragma unroll
    for (int m = 0; m < 2; ++m)
#pragma unroll
        for (int hh = 0; hh < 2; ++hh) {
            rs[m][hh] += __shfl_xor_sync(0xffffffffu, rs[m][hh], 1);
            rs[m][hh] += __shfl_xor_sync(0xffffffffu, rs[m][hh], 2);
        }
    if ((lane & 3) == 0) {
        int head = xh * 2 + nw;
        float bias = __ldg(&b2[head]);
#pragma unroll
        for (int m = 0; m < 2; ++m) {
            int node = n0 + mw * 32 + m * 16 + (lane >> 2);
            if (node < n)
                ((float*)d_h0)[node * NH + head] = rs[m][0] + bias;
            if (node + 8 < n)
                ((float*)d_h0)[(node + 8) * NH + head] = rs[m][1] + bias;
        }
    }
}

// ---------------- gather layer 0: per-head num/den from CSR -> h1s --------------
__global__ void k_gather0(int n) {
    __shared__ float4 w[REL];
    if (threadIdx.x < REL) w[threadIdx.x] = ((const float4*)d_w)[threadIdx.x];
    __syncthreads();
    int i = blockIdx.x * blockDim.x + threadIdx.x;
    if (i >= n) return;
    unsigned b = d_off[i], eend = d_off[i + 1];
    float4 num = make_float4(0.f, 0.f, 0.f, 0.f);
    float4 den = num;
    for (unsigned j = b; j < eend; ++j) {
        unsigned p = d_edges[j];
        float4 wv = w[p >> 17];
        float4 hs = d_h0[p & 0x1FFFFu];
        num.x += wv.x * hs.x; num.y += wv.y * hs.y;
        num.z += wv.z * hs.z; num.w += wv.w * hs.w;
        den.x += wv.x; den.y += wv.y; den.z += wv.z; den.w += wv.w;
    }
    float s = 0.f, r;
    r = den.x > 0.f ? num.x / den.x : 0.f; s += r > 0.f ? r : 0.f;
    r = den.y > 0.f ? num.y / den.y : 0.f; s += r > 0.f ? r : 0.f;
    r = den.z > 0.f ? num.z / den.z : 0.f; s += r > 0.f ? r : 0.f;
    r = den.w > 0.f ? num.w / den.w : 0.f; s += r > 0.f ? r : 0.f;
    d_h1s[i] = 0.25f * s;
}

// ---------------- gather layers 1/2 (scalar source) ------------------------------
template <int FINAL>
__global__ void k_gather12(int n, const float* __restrict__ centrality,
                           const float* __restrict__ gamma,
                           const float* __restrict__ beta,
                           float* __restrict__ out) {
    __shared__ float4 w[REL];
    if (threadIdx.x < REL)
        w[threadIdx.x] = ((const float4*)d_w)[(FINAL ? 2 : 1) * REL + threadIdx.x];
    __syncthreads();
    int i = blockIdx.x * blockDim.x + threadIdx.x;
    if (i >= n) return;
    unsigned b = d_off[i], eend = d_off[i + 1];
    float4 num = make_float4(0.f, 0.f, 0.f, 0.f);
    float4 den = num;
    const float* hv = FINAL ? d_h2s : d_h1s;
    for (unsigned j = b; j < eend; ++j) {
        unsigned p = d_edges[j];
        float4 wv = w[p >> 17];
        float hs = hv[p & 0x1FFFFu];
        num.x += wv.x * hs; num.y += wv.y * hs;
        num.z += wv.z * hs; num.w += wv.w * hs;
        den.x += wv.x; den.y += wv.y; den.z += wv.z; den.w += wv.w;
    }
    if (!FINAL) {
        float s = 0.f, r;
        r = den.x > 0.f ? num.x / den.x : 0.f; s += r > 0.f ? r : 0.f;
        r = den.y > 0.f ? num.y / den.y : 0.f; s += r > 0.f ? r : 0.f;
        r = den.z > 0.f ? num.z / den.z : 0.f; s += r > 0.f ? r : 0.f;
        r = den.w > 0.f ? num.w / den.w : 0.f; s += r > 0.f ? r : 0.f;
        d_h2s[i] = 0.25f * s;
    } else {
        float c = centrality[i];
        float s = 0.f, r;
        r = den.x > 0.f ? num.x / den.x : 0.f; r = r > 0.f ? r : 0.f;
        s += (c * __ldg(&gamma[0]) + __ldg(&beta[0])) * r;
        r = den.y > 0.f ? num.y / den.y : 0.f; r = r > 0.f ? r : 0.f;
        s += (c * __ldg(&gamma[1]) + __ldg(&beta[1])) * r;
        r = den.z > 0.f ? num.z / den.z : 0.f; r = r > 0.f ? r : 0.f;
        s += (c * __ldg(&gamma[2]) + __ldg(&beta[2])) * r;
        r = den.w > 0.f ? num.w / den.w : 0.f; r = r > 0.f ? r : 0.f;
        s += (c * __ldg(&gamma[3]) + __ldg(&beta[3])) * r;
        float v = 0.25f * s;
        out[i] = (v > 0.f) ? v : 0.01f * v;
    }
}

// ---------------- launch -------------------------------------------------------
extern "C" void kernel_launch(void* const* d_in, const int* in_sizes, int n_in,
                              void* d_out, int out_size) {
    const float* inputs     = (const float*)d_in[0];
    const float* centrality = (const float*)d_in[1];
    const float* W1         = (const float*)d_in[2];
    const float* b1         = (const float*)d_in[3];
    const float* W2         = (const float*)d_in[4];
    const float* b2         = (const float*)d_in[5];
    const float* rel_emb    = (const float*)d_in[6];
    const float* W_pred     = (const float*)d_in[7];
    const float* gamma      = (const float*)d_in[8];
    const float* beta       = (const float*)d_in[9];
    const int*   et         = (const int*)d_in[10];
    const int*   src        = (const int*)d_in[11];
    const int*   dst        = (const int*)d_in[12];

    const int n = in_sizes[1];          // N
    const int e = in_sizes[10];         // E
    float* out = (float*)d_out;

    const int EB = (e + 255) / 256;
    const int NB = (n + 255) / 256;
    const int nblk = (n + 1023) / 1024;

    k_init<<<512, 256>>>(rel_emb, W_pred, n);
    k_hist<<<EB, 256>>>(dst, e);
    k_scanA<<<nblk, 1024>>>(n);
    k_scanB<<<1, 128>>>(nblk);
    k_scanC<<<nblk, 1024>>>(n);
    k_scatter<<<EB, 256>>>(et, src, dst, e);

    k_mlp_mma<<<dim3(2, (n + 127) / 128), 256>>>(inputs, W1, b1, W2, b2, n);

    k_gather0<<<NB, 256>>>(n);
    k_gather12<0><<<NB, 256>>>(n, centrality, gamma, beta, out);
    k_gather12<1><<<NB, 256>>>(n, centrality, gamma, beta, out);
}

// round 13
// speedup vs baseline: 1.0498x; 1.0498x over previous
#include <cuda_runtime.h>
#include <cuda_bf16.h>
#include <cstdint>

#define N_MAX   100000
#define NH      4
#define INDIM   128
#define REL     50
#define REL_P   52          // padded S row (16B-aligned float4 chunks)
#define PD      16
#define CW      13          // ceil(REL/4) packed-count words per node

// ---------------- scratch (device globals; no allocation allowed) -------------
__device__ __align__(16) float  d_w[3 * REL * NH];   // exp(leaky(rel_emb@W_pred))
__device__ __align__(16) float4 d_h0[N_MAX];         // MLP output (N,4)
__device__ unsigned d_cntp[N_MAX * CW];              // byte-packed type histogram
__device__ __align__(16) float4 d_num0[N_MAX];
__device__ __align__(16) float4 d_den1[N_MAX];
__device__ __align__(16) float4 d_den2[N_MAX];
__device__ __align__(16) float d_S[N_MAX * REL_P];   // per-(node,type) scalar sums
__device__ float d_h1s[N_MAX];
__device__ float d_h2s[N_MAX];

// ---------------- init: tables + zero scratch (every launch, graph-safe) -------
__global__ void k_init(const float* __restrict__ rel_emb,
                       const float* __restrict__ W_pred, int n) {
    int gt = blockIdx.x * blockDim.x + threadIdx.x;
    if (gt < 3 * REL * NH) {
        int l = gt / (REL * NH);
        int r = gt - l * (REL * NH);
        int t = r >> 2, h = r & 3;
        float acc = 0.f;
#pragma unroll
        for (int p = 0; p < PD; ++p)
            acc += rel_emb[t * PD + p] * W_pred[l * PD * NH + p * NH + h];
        float e = acc > 0.f ? acc : 0.2f * acc;
        d_w[gt] = expf(e);
    }
    int stride = gridDim.x * blockDim.x;
    for (int i = gt; i < n * CW; i += stride) d_cntp[i] = 0u;
    float4 z = make_float4(0.f, 0.f, 0.f, 0.f);
    for (int i = gt; i < n; i += stride) d_num0[i] = z;
    float4* Sv = (float4*)d_S;
    for (int i = gt; i < n * (REL_P / 4); i += stride) Sv[i] = z;
}

// ================= HMMA (mma.sync) split-bf16 MLP ==============================
#define LDP    40
#define MATB   (128 * LDP * 2)
#define OFF_AH 0
#define OFF_AL MATB
#define OFF_BH (2 * MATB)
#define OFF_BL (3 * MATB)
#define OFF_B1 (4 * MATB)
#define OFF_W2 (OFF_B1 + 512)
#define SM_TOT (OFF_W2 + 512)

__device__ __forceinline__ uint32_t smem_u32(const void* p) {
    uint32_t a;
    asm("{ .reg .u64 t; cvta.to.shared.u64 t, %1; cvt.u32.u64 %0, t; }"
        : "=r"(a) : "l"(p));
    return a;
}
__device__ __forceinline__ uint32_t pack_bf2(__nv_bfloat16 lo, __nv_bfloat16 hi) {
    return (uint32_t)__bfloat16_as_ushort(lo) |
           ((uint32_t)__bfloat16_as_ushort(hi) << 16);
}
#define LDSM_X4(R0, R1, R2, R3, ADDR)                                         \
    asm volatile("ldmatrix.sync.aligned.m8n8.x4.shared.b16 {%0,%1,%2,%3}, [%4];" \
                 : "=r"(R0), "=r"(R1), "=r"(R2), "=r"(R3) : "r"(ADDR))

__device__ __forceinline__ void mma_bf16(float* d, const uint32_t* a,
                                         const uint32_t* b) {
    asm volatile(
        "mma.sync.aligned.m16n8k16.row.col.f32.bf16.bf16.f32 "
        "{%0,%1,%2,%3}, {%4,%5,%6,%7}, {%8,%9}, {%0,%1,%2,%3};"
        : "+f"(d[0]), "+f"(d[1]), "+f"(d[2]), "+f"(d[3])
        : "r"(a[0]), "r"(a[1]), "r"(a[2]), "r"(a[3]), "r"(b[0]), "r"(b[1]));
}

__global__ void __launch_bounds__(256) k_mlp_mma(
    const float* __restrict__ inputs, const float* __restrict__ W1,
    const float* __restrict__ b1, const float* __restrict__ W2,
    const float* __restrict__ b2, int n) {
    __shared__ __align__(16) char sm[SM_TOT];
    const int tid = threadIdx.x;
    const int lane = tid & 31, wid = tid >> 5;
    const int mw = wid & 3, nw = wid >> 2;
    const int xh = blockIdx.x;
    const int n0 = blockIdx.y * 128;

    float* b1s = (float*)(sm + OFF_B1);
    float* w2s = (float*)(sm + OFF_W2);
    if (tid < 128) {
        b1s[tid] = b1[xh * 128 + tid];
        w2s[tid] = W2[xh * 128 + tid];
    }

    float acc[2][8][4];
#pragma unroll
    for (int m = 0; m < 2; ++m)
#pragma unroll
        for (int t = 0; t < 8; ++t)
#pragma unroll
            for (int r = 0; r < 4; ++r) acc[m][t][r] = 0.f;

    const uint32_t sb = smem_u32(sm);
    const int rowA = mw * 32 + (lane & 15);
    const int kA = (lane >> 4) * 8;
    uint32_t aof[2];
#pragma unroll
    for (int m = 0; m < 2; ++m)
        aof[m] = sb + OFF_AH + (uint32_t)(((rowA + m * 16) * LDP + kA) * 2);
    const int colB = nw * 64 + (lane >> 4) * 8 + (lane & 7);
    const int kB = ((lane >> 3) & 1) * 8;
    uint32_t bof[4];
#pragma unroll
    for (int t = 0; t < 4; ++t)
        bof[t] = sb + OFF_BH + (uint32_t)(((colB + t * 16) * LDP + kB) * 2);

    const int sr = tid >> 1;
    const int skb = (tid & 1) * 16;

    for (int kc = 0; kc < 4; ++kc) {
        {
            int node = n0 + sr;
            const float* p = inputs + (size_t)node * INDIM + kc * 32 + skb;
            uint32_t* ah = (uint32_t*)(sm + OFF_AH + (sr * LDP + skb) * 2);
            uint32_t* al = (uint32_t*)(sm + OFF_AL + (sr * LDP + skb) * 2);
            bool ok = node < n;
#pragma unroll
            for (int j = 0; j < 16; j += 4) {
                float4 v = ok ? *(const float4*)(p + j)
                              : make_float4(0.f, 0.f, 0.f, 0.f);
                __nv_bfloat16 hx = __float2bfloat16(v.x);
                __nv_bfloat16 hy = __float2bfloat16(v.y);
                __nv_bfloat16 hz = __float2bfloat16(v.z);
                __nv_bfloat16 hw = __float2bfloat16(v.w);
                ah[j / 2]     = pack_bf2(hx, hy);
                ah[j / 2 + 1] = pack_bf2(hz, hw);
                al[j / 2] = pack_bf2(__float2bfloat16(v.x - __bfloat162float(hx)),
                                     __float2bfloat16(v.y - __bfloat162float(hy)));
                al[j / 2 + 1] =
                    pack_bf2(__float2bfloat16(v.z - __bfloat162float(hz)),
                             __float2bfloat16(v.w - __bfloat162float(hw)));
            }
        }
        {
            const float* q =
                W1 + (size_t)(xh * 128 + sr) * INDIM + kc * 32 + skb;
            uint32_t* bh = (uint32_t*)(sm + OFF_BH + (sr * LDP + skb) * 2);
            uint32_t* bl = (uint32_t*)(sm + OFF_BL + (sr * LDP + skb) * 2);
#pragma unroll
            for (int j = 0; j < 16; j += 4) {
                float4 v = *(const float4*)(q + j);
                __nv_bfloat16 hx = __float2bfloat16(v.x);
                __nv_bfloat16 hy = __float2bfloat16(v.y);
                __nv_bfloat16 hz = __float2bfloat16(v.z);
                __nv_bfloat16 hw = __float2bfloat16(v.w);
                bh[j / 2]     = pack_bf2(hx, hy);
                bh[j / 2 + 1] = pack_bf2(hz, hw);
                bl[j / 2] = pack_bf2(__float2bfloat16(v.x - __bfloat162float(hx)),
                                     __float2bfloat16(v.y - __bfloat162float(hy)));
                bl[j / 2 + 1] =
                    pack_bf2(__float2bfloat16(v.z - __bfloat162float(hz)),
                             __float2bfloat16(v.w - __bfloat162float(hw)));
            }
        }
        __syncthreads();

#pragma unroll
        for (int pass = 0; pass < 3; ++pass) {
            uint32_t ab = (pass == 1) ? (uint32_t)MATB : 0u;
            uint32_t bb = (pass == 2) ? (uint32_t)MATB : 0u;
#pragma unroll
            for (int ks = 0; ks < 2; ++ks) {
                uint32_t a[2][4], b[8][2];
                LDSM_X4(a[0][0], a[0][1], a[0][2], a[0][3],
                        aof[0] + ab + ks * 32);
                LDSM_X4(a[1][0], a[1][1], a[1][2], a[1][3],
                        aof[1] + ab + ks * 32);
#pragma unroll
                for (int t = 0; t < 4; ++t) {
                    uint32_t r0, r1, r2, r3;
                    LDSM_X4(r0, r1, r2, r3, bof[t] + bb + ks * 32);
                    b[2 * t][0] = r0; b[2 * t][1] = r1;
                    b[2 * t + 1][0] = r2; b[2 * t + 1][1] = r3;
                }
#pragma unroll
                for (int m = 0; m < 2; ++m)
#pragma unroll
                    for (int t = 0; t < 8; ++t) mma_bf16(acc[m][t], a[m], b[t]);
            }
        }
        __syncthreads();
    }

    float rs[2][2] = {{0.f, 0.f}, {0.f, 0.f}};
#pragma unroll
    for (int t = 0; t < 8; ++t) {
        int c = nw * 64 + t * 8 + (lane & 3) * 2;
        float bb0 = b1s[c], bb1 = b1s[c + 1];
        float ww0 = w2s[c], ww1 = w2s[c + 1];
#pragma unroll
        for (int m = 0; m < 2; ++m) {
            float v;
            v = acc[m][t][0] + bb0; v = v > 0.f ? v : 0.f; rs[m][0] += v * ww0;
            v = acc[m][t][1] + bb1; v = v > 0.f ? v : 0.f; rs[m][0] += v * ww1;
            v = acc[m][t][2] + bb0; v = v > 0.f ? v : 0.f; rs[m][1] += v * ww0;
            v = acc[m][t][3] + bb1; v = v > 0.f ? v : 0.f; rs[m][1] += v * ww1;
        }
    }
#pragma unroll
    for (int m = 0; m < 2; ++m)
#pragma unroll
        for (int hh = 0; hh < 2; ++hh) {
            rs[m][hh] += __shfl_xor_sync(0xffffffffu, rs[m][hh], 1);
            rs[m][hh] += __shfl_xor_sync(0xffffffffu, rs[m][hh], 2);
        }
    if ((lane & 3) == 0) {
        int head = xh * 2 + nw;
        float bias = __ldg(&b2[head]);
#pragma unroll
        for (int m = 0; m < 2; ++m) {
            int node = n0 + mw * 32 + m * 16 + (lane >> 2);
            if (node < n)
                ((float*)d_h0)[node * NH + head] = rs[m][0] + bias;
            if (node + 8 < n)
                ((float*)d_h0)[(node + 8) * NH + head] = rs[m][1] + bias;
        }
    }
}

// ---------------- layer 0 edge pass: packed histogram + vec4 numerators -------
__global__ void k_edge0(const int* __restrict__ et, const int* __restrict__ src,
                        const int* __restrict__ dst, int e) {
    __shared__ float4 w0[REL];
    if (threadIdx.x < REL) w0[threadIdx.x] = ((const float4*)d_w)[threadIdx.x];
    __syncthreads();
    int i = blockIdx.x * blockDim.x + threadIdx.x;
    if (i >= e) return;
    int t = et[i], s = src[i], d = dst[i];
    atomicAdd(&d_cntp[d * CW + (t >> 2)], 1u << (8 * (t & 3)));
    float4 hs = d_h0[s];
    float4 wv = w0[t];
    atomicAdd(&d_num0[d],
              make_float4(wv.x * hs.x, wv.y * hs.y, wv.z * hs.z, wv.w * hs.w));
}

// ---------------- layers 1/2 edge pass: 1-word scalar scatter into S ----------
template <int WHICH>
__global__ void k_edgeS(const int* __restrict__ et, const int* __restrict__ src,
                        const int* __restrict__ dst, int e) {
    int i = blockIdx.x * blockDim.x + threadIdx.x;
    if (i >= e) return;
    float hs = WHICH ? d_h2s[src[i]] : d_h1s[src[i]];
    atomicAdd(&d_S[dst[i] * REL_P + et[i]], hs);
}

// ---------------- combine 0: dens for ALL layers from histogram + h1s ---------
__global__ void k_combine0(int n) {
    __shared__ float4 w[3 * REL];
    if (threadIdx.x < 3 * REL) w[threadIdx.x] = ((const float4*)d_w)[threadIdx.x];
    __syncthreads();
    int i = blockIdx.x * blockDim.x + threadIdx.x;
    if (i >= n) return;
    float4 de0 = make_float4(0.f, 0.f, 0.f, 0.f);
    float4 de1 = de0, de2 = de0;
#pragma unroll
    for (int j = 0; j < CW; ++j) {
        unsigned cw = d_cntp[i * CW + j];
#pragma unroll
        for (int b = 0; b < 4; ++b) {
            int t = j * 4 + b;
            if (t >= REL) break;
            float c = (float)((cw >> (8 * b)) & 0xffu);
            float4 w0 = w[t], w1 = w[REL + t], w2 = w[2 * REL + t];
            de0.x += c * w0.x; de0.y += c * w0.y; de0.z += c * w0.z; de0.w += c * w0.w;
            de1.x += c * w1.x; de1.y += c * w1.y; de1.z += c * w1.z; de1.w += c * w1.w;
            de2.x += c * w2.x; de2.y += c * w2.y; de2.z += c * w2.z; de2.w += c * w2.w;
        }
    }
    d_den1[i] = de1;
    d_den2[i] = de2;
    float4 nu = d_num0[i];
    float s = 0.f, r;
    r = de0.x > 0.f ? nu.x / de0.x : 0.f; s += r > 0.f ? r : 0.f;
    r = de0.y > 0.f ? nu.y / de0.y : 0.f; s += r > 0.f ? r : 0.f;
    r = de0.z > 0.f ? nu.z / de0.z : 0.f; s += r > 0.f ? r : 0.f;
    r = de0.w > 0.f ? nu.w / de0.w : 0.f; s += r > 0.f ? r : 0.f;
    d_h1s[i] = 0.25f * s;
}

// ---------------- combine 1: num1 from S (zeroing S for layer 2) -> h2s --------
__global__ void k_combine1(int n) {
    __shared__ float4 w[REL_P];
    if (threadIdx.x < REL_P)
        w[threadIdx.x] = (threadIdx.x < REL)
                             ? ((const float4*)d_w)[REL + threadIdx.x]
                             : make_float4(0.f, 0.f, 0.f, 0.f);
    __syncthreads();
    int i = blockIdx.x * blockDim.x + threadIdx.x;
    if (i >= n) return;
    float4* Srow = (float4*)&d_S[(size_t)i * REL_P];
    const float4 z = make_float4(0.f, 0.f, 0.f, 0.f);
    float4 nu = z;
#pragma unroll
    for (int j = 0; j < REL_P / 4; ++j) {
        float4 sv = Srow[j];
        Srow[j] = z;                                  // reset S for layer 2
        float4 wa = w[4 * j], wb = w[4 * j + 1], wc = w[4 * j + 2],
               wd = w[4 * j + 3];
        nu.x += sv.x * wa.x + sv.y * wb.x + sv.z * wc.x + sv.w * wd.x;
        nu.y += sv.x * wa.y + sv.y * wb.y + sv.z * wc.y + sv.w * wd.y;
        nu.z += sv.x * wa.z + sv.y * wb.z + sv.z * wc.z + sv.w * wd.z;
        nu.w += sv.x * wa.w + sv.y * wb.w + sv.z * wc.w + sv.w * wd.w;
    }
    float4 de = d_den1[i];
    float s = 0.f, r;
    r = de.x > 0.f ? nu.x / de.x : 0.f; s += r > 0.f ? r : 0.f;
    r = de.y > 0.f ? nu.y / de.y : 0.f; s += r > 0.f ? r : 0.f;
    r = de.z > 0.f ? nu.z / de.z : 0.f; s += r > 0.f ? r : 0.f;
    r = de.w > 0.f ? nu.w / de.w : 0.f; s += r > 0.f ? r : 0.f;
    d_h2s[i] = 0.25f * s;
}

// ---------------- combine 2: num2 from S + final epilogue ----------------------
__global__ void k_combine2(int n, const float* __restrict__ centrality,
                           const float* __restrict__ gamma,
                           const float* __restrict__ beta,
                           float* __restrict__ out) {
    __shared__ float4 w[REL_P];
    if (threadIdx.x < REL_P)
        w[threadIdx.x] = (threadIdx.x < REL)
                             ? ((const float4*)d_w)[2 * REL + threadIdx.x]
                             : make_float4(0.f, 0.f, 0.f, 0.f);
    __syncthreads();
    int i = blockIdx.x * blockDim.x + threadIdx.x;
    if (i >= n) return;
    const float4* Srow = (const float4*)&d_S[(size_t)i * REL_P];
    float4 nu = make_float4(0.f, 0.f, 0.f, 0.f);
#pragma unroll
    for (int j = 0; j < REL_P / 4; ++j) {
        float4 sv = Srow[j];
        float4 wa = w[4 * j], wb = w[4 * j + 1], wc = w[4 * j + 2],
               wd = w[4 * j + 3];
        nu.x += sv.x * wa.x + sv.y * wb.x + sv.z * wc.x + sv.w * wd.x;
        nu.y += sv.x * wa.y + sv.y * wb.y + sv.z * wc.y + sv.w * wd.y;
        nu.z += sv.x * wa.z + sv.y * wb.z + sv.z * wc.z + sv.w * wd.z;
        nu.w += sv.x * wa.w + sv.y * wb.w + sv.z * wc.w + sv.w * wd.w;
    }
    float4 de = d_den2[i];
    float c = centrality[i];
    float s = 0.f, r;
    r = de.x > 0.f ? nu.x / de.x : 0.f; r = r > 0.f ? r : 0.f;
    s += (c * __ldg(&gamma[0]) + __ldg(&beta[0])) * r;
    r = de.y > 0.f ? nu.y / de.y : 0.f; r = r > 0.f ? r : 0.f;
    s += (c * __ldg(&gamma[1]) + __ldg(&beta[1])) * r;
    r = de.z > 0.f ? nu.z / de.z : 0.f; r = r > 0.f ? r : 0.f;
    s += (c * __ldg(&gamma[2]) + __ldg(&beta[2])) * r;
    r = de.w > 0.f ? nu.w / de.w : 0.f; r = r > 0.f ? r : 0.f;
    s += (c * __ldg(&gamma[3]) + __ldg(&beta[3])) * r;
    float v = 0.25f * s;
    out[i] = (v > 0.f) ? v : 0.01f * v;
}

// ---------------- launch -------------------------------------------------------
extern "C" void kernel_launch(void* const* d_in, const int* in_sizes, int n_in,
                              void* d_out, int out_size) {
    const float* inputs     = (const float*)d_in[0];
    const float* centrality = (const float*)d_in[1];
    const float* W1         = (const float*)d_in[2];
    const float* b1         = (const float*)d_in[3];
    const float* W2         = (const float*)d_in[4];
    const float* b2         = (const float*)d_in[5];
    const float* rel_emb    = (const float*)d_in[6];
    const float* W_pred     = (const float*)d_in[7];
    const float* gamma      = (const float*)d_in[8];
    const float* beta       = (const float*)d_in[9];
    const int*   et         = (const int*)d_in[10];
    const int*   src        = (const int*)d_in[11];
    const int*   dst        = (const int*)d_in[12];

    const int n = in_sizes[1];          // N
    const int e = in_sizes[10];         // E
    float* out = (float*)d_out;

    const int EB = (e + 255) / 256;
    const int NB = (n + 255) / 256;

    k_init<<<4096, 256>>>(rel_emb, W_pred, n);
    k_mlp_mma<<<dim3(2, (n + 127) / 128), 256>>>(inputs, W1, b1, W2, b2, n);

    // layer 0 (per-head sources: 5-word atomics, irreducible)
    k_edge0<<<EB, 256>>>(et, src, dst, e);
    k_combine0<<<NB, 256>>>(n);

    // layer 1 (scalar sources: 1-word atomics into S)
    k_edgeS<0><<<EB, 256>>>(et, src, dst, e);
    k_combine1<<<NB, 256>>>(n);

    // layer 2 + epilogue
    k_edgeS<1><<<EB, 256>>>(et, src, dst, e);
    k_combine2<<<NB, 256>>>(n, centrality, gamma, beta, out);
}

// round 14
// speedup vs baseline: 1.1560x; 1.1012x over previous
#include <cuda_runtime.h>
#include <cuda_bf16.h>
#include <cstdint>

#define N_MAX   100000
#define NH      4
#define INDIM   128
#define REL     50
#define PD      16
#define CW      13          // ceil(REL/4) packed-count words per node

#define HIST_BLOCKS 1024
#define ZERO_BLOCKS 256

// ---------------- scratch (device globals; no allocation allowed) -------------
__device__ __align__(16) float  d_w[3 * REL * NH];   // exp(leaky(rel_emb@W_pred))
__device__ __align__(16) float4 d_h0[N_MAX];         // MLP output (N,4)
__device__ unsigned d_cntp[N_MAX * CW];              // byte-packed type histogram
__device__ __align__(16) float4 d_num0[N_MAX];
__device__ __align__(16) float4 d_num1[N_MAX];
__device__ __align__(16) float4 d_num2[N_MAX];
__device__ __align__(16) float4 d_den0[N_MAX];
__device__ __align__(16) float4 d_den1[N_MAX];
__device__ __align__(16) float4 d_den2[N_MAX];
__device__ float d_h1s[N_MAX];
__device__ float d_h2s[N_MAX];

// ---------------- init: tables + zero cnt histogram ----------------------------
__global__ void k_init(const float* __restrict__ rel_emb,
                       const float* __restrict__ W_pred, int n) {
    int gt = blockIdx.x * blockDim.x + threadIdx.x;
    if (gt < 3 * REL * NH) {
        int l = gt / (REL * NH);
        int r = gt - l * (REL * NH);
        int t = r >> 2, h = r & 3;
        float acc = 0.f;
#pragma unroll
        for (int p = 0; p < PD; ++p)
            acc += rel_emb[t * PD + p] * W_pred[l * PD * NH + p * NH + h];
        float e = acc > 0.f ? acc : 0.2f * acc;
        d_w[gt] = expf(e);
    }
    int stride = gridDim.x * blockDim.x;
    for (int i = gt; i < n * CW; i += stride) d_cntp[i] = 0u;
}

// ================= fat kernel A: MLP (tensor) + histogram (L2 atomics) ========
//                                + num zeroing (DRAM), block-specialized
#define LDP    40
#define MATB   (128 * LDP * 2)
#define OFF_AH 0
#define OFF_AL MATB
#define OFF_BH (2 * MATB)
#define OFF_BL (3 * MATB)
#define OFF_B1 (4 * MATB)
#define OFF_W2 (OFF_B1 + 512)
#define SM_TOT (OFF_W2 + 512)

__device__ __forceinline__ uint32_t smem_u32(const void* p) {
    uint32_t a;
    asm("{ .reg .u64 t; cvta.to.shared.u64 t, %1; cvt.u32.u64 %0, t; }"
        : "=r"(a) : "l"(p));
    return a;
}
__device__ __forceinline__ uint32_t pack_bf2(__nv_bfloat16 lo, __nv_bfloat16 hi) {
    return (uint32_t)__bfloat16_as_ushort(lo) |
           ((uint32_t)__bfloat16_as_ushort(hi) << 16);
}
#define LDSM_X4(R0, R1, R2, R3, ADDR)                                         \
    asm volatile("ldmatrix.sync.aligned.m8n8.x4.shared.b16 {%0,%1,%2,%3}, [%4];" \
                 : "=r"(R0), "=r"(R1), "=r"(R2), "=r"(R3) : "r"(ADDR))

__device__ __forceinline__ void mma_bf16(float* d, const uint32_t* a,
                                         const uint32_t* b) {
    asm volatile(
        "mma.sync.aligned.m16n8k16.row.col.f32.bf16.bf16.f32 "
        "{%0,%1,%2,%3}, {%4,%5,%6,%7}, {%8,%9}, {%0,%1,%2,%3};"
        : "+f"(d[0]), "+f"(d[1]), "+f"(d[2]), "+f"(d[3])
        : "r"(a[0]), "r"(a[1]), "r"(a[2]), "r"(a[3]), "r"(b[0]), "r"(b[1]));
}

__global__ void __launch_bounds__(256) k_fatA(
    const float* __restrict__ inputs, const float* __restrict__ W1,
    const float* __restrict__ b1, const float* __restrict__ W2,
    const float* __restrict__ b2, const int* __restrict__ et,
    const int* __restrict__ dst, int n, int e, int mlp_blocks) {
    __shared__ __align__(16) char sm[SM_TOT];
    const int tid = threadIdx.x;

    // ---- segment 2: histogram blocks (grid-stride over edges) ----
    if (blockIdx.x >= mlp_blocks) {
        int seg = blockIdx.x - mlp_blocks;
        if (seg < HIST_BLOCKS) {
            for (int i = seg * 256 + tid; i < e; i += HIST_BLOCKS * 256) {
                int t = et[i];
                atomicAdd(&d_cntp[dst[i] * CW + (t >> 2)], 1u << (8 * (t & 3)));
            }
        } else {
            // ---- segment 3: zero num arrays ----
            int z = seg - HIST_BLOCKS;
            float4 zv = make_float4(0.f, 0.f, 0.f, 0.f);
            for (int i = z * 256 + tid; i < n; i += ZERO_BLOCKS * 256) {
                d_num0[i] = zv; d_num1[i] = zv; d_num2[i] = zv;
            }
        }
        return;
    }

    // ---- segment 1: HMMA split-bf16 MLP ----
    const int lane = tid & 31, wid = tid >> 5;
    const int mw = wid & 3, nw = wid >> 2;
    const int xh = blockIdx.x & 1;
    const int n0 = (blockIdx.x >> 1) * 128;

    float* b1s = (float*)(sm + OFF_B1);
    float* w2s = (float*)(sm + OFF_W2);
    if (tid < 128) {
        b1s[tid] = b1[xh * 128 + tid];
        w2s[tid] = W2[xh * 128 + tid];
    }

    float acc[2][8][4];
#pragma unroll
    for (int m = 0; m < 2; ++m)
#pragma unroll
        for (int t = 0; t < 8; ++t)
#pragma unroll
            for (int r = 0; r < 4; ++r) acc[m][t][r] = 0.f;

    const uint32_t sb = smem_u32(sm);
    const int rowA = mw * 32 + (lane & 15);
    const int kA = (lane >> 4) * 8;
    uint32_t aof[2];
#pragma unroll
    for (int m = 0; m < 2; ++m)
        aof[m] = sb + OFF_AH + (uint32_t)(((rowA + m * 16) * LDP + kA) * 2);
    const int colB = nw * 64 + (lane >> 4) * 8 + (lane & 7);
    const int kB = ((lane >> 3) & 1) * 8;
    uint32_t bof[4];
#pragma unroll
    for (int t = 0; t < 4; ++t)
        bof[t] = sb + OFF_BH + (uint32_t)(((colB + t * 16) * LDP + kB) * 2);

    const int sr = tid >> 1;
    const int skb = (tid & 1) * 16;

    for (int kc = 0; kc < 4; ++kc) {
        {
            int node = n0 + sr;
            const float* p = inputs + (size_t)node * INDIM + kc * 32 + skb;
            uint32_t* ah = (uint32_t*)(sm + OFF_AH + (sr * LDP + skb) * 2);
            uint32_t* al = (uint32_t*)(sm + OFF_AL + (sr * LDP + skb) * 2);
            bool ok = node < n;
#pragma unroll
            for (int j = 0; j < 16; j += 4) {
                float4 v = ok ? *(const float4*)(p + j)
                              : make_float4(0.f, 0.f, 0.f, 0.f);
                __nv_bfloat16 hx = __float2bfloat16(v.x);
                __nv_bfloat16 hy = __float2bfloat16(v.y);
                __nv_bfloat16 hz = __float2bfloat16(v.z);
                __nv_bfloat16 hw = __float2bfloat16(v.w);
                ah[j / 2]     = pack_bf2(hx, hy);
                ah[j / 2 + 1] = pack_bf2(hz, hw);
                al[j / 2] = pack_bf2(__float2bfloat16(v.x - __bfloat162float(hx)),
                                     __float2bfloat16(v.y - __bfloat162float(hy)));
                al[j / 2 + 1] =
                    pack_bf2(__float2bfloat16(v.z - __bfloat162float(hz)),
                             __float2bfloat16(v.w - __bfloat162float(hw)));
            }
        }
        {
            const float* q =
                W1 + (size_t)(xh * 128 + sr) * INDIM + kc * 32 + skb;
            uint32_t* bh = (uint32_t*)(sm + OFF_BH + (sr * LDP + skb) * 2);
            uint32_t* bl = (uint32_t*)(sm + OFF_BL + (sr * LDP + skb) * 2);
#pragma unroll
            for (int j = 0; j < 16; j += 4) {
                float4 v = *(const float4*)(q + j);
                __nv_bfloat16 hx = __float2bfloat16(v.x);
                __nv_bfloat16 hy = __float2bfloat16(v.y);
                __nv_bfloat16 hz = __float2bfloat16(v.z);
                __nv_bfloat16 hw = __float2bfloat16(v.w);
                bh[j / 2]     = pack_bf2(hx, hy);
                bh[j / 2 + 1] = pack_bf2(hz, hw);
                bl[j / 2] = pack_bf2(__float2bfloat16(v.x - __bfloat162float(hx)),
                                     __float2bfloat16(v.y - __bfloat162float(hy)));
                bl[j / 2 + 1] =
                    pack_bf2(__float2bfloat16(v.z - __bfloat162float(hz)),
                             __float2bfloat16(v.w - __bfloat162float(hw)));
            }
        }
        __syncthreads();

#pragma unroll
        for (int pass = 0; pass < 3; ++pass) {
            uint32_t ab = (pass == 1) ? (uint32_t)MATB : 0u;
            uint32_t bb = (pass == 2) ? (uint32_t)MATB : 0u;
#pragma unroll
            for (int ks = 0; ks < 2; ++ks) {
                uint32_t a[2][4], b[8][2];
                LDSM_X4(a[0][0], a[0][1], a[0][2], a[0][3],
                        aof[0] + ab + ks * 32);
                LDSM_X4(a[1][0], a[1][1], a[1][2], a[1][3],
                        aof[1] + ab + ks * 32);
#pragma unroll
                for (int t = 0; t < 4; ++t) {
                    uint32_t r0, r1, r2, r3;
                    LDSM_X4(r0, r1, r2, r3, bof[t] + bb + ks * 32);
                    b[2 * t][0] = r0; b[2 * t][1] = r1;
                    b[2 * t + 1][0] = r2; b[2 * t + 1][1] = r3;
                }
#pragma unroll
                for (int m = 0; m < 2; ++m)
#pragma unroll
                    for (int t = 0; t < 8; ++t) mma_bf16(acc[m][t], a[m], b[t]);
            }
        }
        __syncthreads();
    }

    float rs[2][2] = {{0.f, 0.f}, {0.f, 0.f}};
#pragma unroll
    for (int t = 0; t < 8; ++t) {
        int c = nw * 64 + t * 8 + (lane & 3) * 2;
        float bb0 = b1s[c], bb1 = b1s[c + 1];
        float ww0 = w2s[c], ww1 = w2s[c + 1];
#pragma unroll
        for (int m = 0; m < 2; ++m) {
            float v;
            v = acc[m][t][0] + bb0; v = v > 0.f ? v : 0.f; rs[m][0] += v * ww0;
            v = acc[m][t][1] + bb1; v = v > 0.f ? v : 0.f; rs[m][0] += v * ww1;
            v = acc[m][t][2] + bb0; v = v > 0.f ? v : 0.f; rs[m][1] += v * ww0;
            v = acc[m][t][3] + bb1; v = v > 0.f ? v : 0.f; rs[m][1] += v * ww1;
        }
    }
#pragma unroll
    for (int m = 0; m < 2; ++m)
#pragma unroll
        for (int hh = 0; hh < 2; ++hh) {
            rs[m][hh] += __shfl_xor_sync(0xffffffffu, rs[m][hh], 1);
            rs[m][hh] += __shfl_xor_sync(0xffffffffu, rs[m][hh], 2);
        }
    if ((lane & 3) == 0) {
        int head = xh * 2 + nw;
        float bias = __ldg(&b2[head]);
#pragma unroll
        for (int m = 0; m < 2; ++m) {
            int node = n0 + mw * 32 + m * 16 + (lane >> 2);
            if (node < n)
                ((float*)d_h0)[node * NH + head] = rs[m][0] + bias;
            if (node + 8 < n)
                ((float*)d_h0)[(node + 8) * NH + head] = rs[m][1] + bias;
        }
    }
}

// ===== fat kernel B: layer-0 numerator REDs + den0/1/2 from histogram =========
__global__ void k_fatB(const int* __restrict__ et, const int* __restrict__ src,
                       const int* __restrict__ dst, int e, int n,
                       int edge_blocks) {
    __shared__ float4 w[3 * REL];
    if (blockIdx.x < edge_blocks) {
        if (threadIdx.x < REL)
            w[threadIdx.x] = ((const float4*)d_w)[threadIdx.x];
        __syncthreads();
        int i = blockIdx.x * 256 + threadIdx.x;
        if (i >= e) return;
        int t = et[i], s = src[i], d = dst[i];
        float4 hs = d_h0[s];
        float4 wv = w[t];
        atomicAdd(&d_num0[d],
                  make_float4(wv.x * hs.x, wv.y * hs.y, wv.z * hs.z, wv.w * hs.w));
        return;
    }
    // ---- dens blocks: den0/1/2 from packed histogram ----
    if (threadIdx.x < 3 * REL)
        w[threadIdx.x] = ((const float4*)d_w)[threadIdx.x];
    __syncthreads();
    int i = (blockIdx.x - edge_blocks) * 256 + threadIdx.x;
    if (i >= n) return;
    float4 de0 = make_float4(0.f, 0.f, 0.f, 0.f);
    float4 de1 = de0, de2 = de0;
#pragma unroll
    for (int j = 0; j < CW; ++j) {
        unsigned cw = d_cntp[i * CW + j];
#pragma unroll
        for (int b = 0; b < 4; ++b) {
            int t = j * 4 + b;
            if (t >= REL) break;
            float c = (float)((cw >> (8 * b)) & 0xffu);
            float4 w0 = w[t], w1 = w[REL + t], w2 = w[2 * REL + t];
            de0.x += c * w0.x; de0.y += c * w0.y; de0.z += c * w0.z; de0.w += c * w0.w;
            de1.x += c * w1.x; de1.y += c * w1.y; de1.z += c * w1.z; de1.w += c * w1.w;
            de2.x += c * w2.x; de2.y += c * w2.y; de2.z += c * w2.z; de2.w += c * w2.w;
        }
    }
    d_den0[i] = de0;
    d_den1[i] = de1;
    d_den2[i] = de2;
}

// ---------------- tiny combine 0: h1s = mean_h relu(num0/den0) -----------------
__global__ void k_h1s(int n) {
    int i = blockIdx.x * blockDim.x + threadIdx.x;
    if (i >= n) return;
    float4 nu = d_num0[i];
    float4 de = d_den0[i];
    float s = 0.f, r;
    r = de.x > 0.f ? nu.x / de.x : 0.f; s += r > 0.f ? r : 0.f;
    r = de.y > 0.f ? nu.y / de.y : 0.f; s += r > 0.f ? r : 0.f;
    r = de.z > 0.f ? nu.z / de.z : 0.f; s += r > 0.f ? r : 0.f;
    r = de.w > 0.f ? nu.w / de.w : 0.f; s += r > 0.f ? r : 0.f;
    d_h1s[i] = 0.25f * s;
}

// ---------------- layers 1/2 edge pass: scalar gather, vec4 scatter -----------
template <int WHICH>
__global__ void k_edgeS(const int* __restrict__ et, const int* __restrict__ src,
                        const int* __restrict__ dst, int e) {
    __shared__ float4 w[REL];
    if (threadIdx.x < REL)
        w[threadIdx.x] = ((const float4*)d_w)[(WHICH ? 2 : 1) * REL + threadIdx.x];
    __syncthreads();
    int i = blockIdx.x * blockDim.x + threadIdx.x;
    if (i >= e) return;
    int t = et[i], d = dst[i];
    float hs = WHICH ? d_h2s[src[i]] : d_h1s[src[i]];
    float4 wv = w[t];
    float4* numl = WHICH ? d_num2 : d_num1;
    atomicAdd(&numl[d], make_float4(wv.x * hs, wv.y * hs, wv.z * hs, wv.w * hs));
}

// ---------------- combine 1: h2s ----------------------------------------------
__global__ void k_combine1(int n) {
    int i = blockIdx.x * blockDim.x + threadIdx.x;
    if (i >= n) return;
    float4 nu = d_num1[i];
    float4 de = d_den1[i];
    float s = 0.f, r;
    r = de.x > 0.f ? nu.x / de.x : 0.f; s += r > 0.f ? r : 0.f;
    r = de.y > 0.f ? nu.y / de.y : 0.f; s += r > 0.f ? r : 0.f;
    r = de.z > 0.f ? nu.z / de.z : 0.f; s += r > 0.f ? r : 0.f;
    r = de.w > 0.f ? nu.w / de.w : 0.f; s += r > 0.f ? r : 0.f;
    d_h2s[i] = 0.25f * s;
}

// ---------------- combine 2: final epilogue ------------------------------------
__global__ void k_combine2(int n, const float* __restrict__ centrality,
                           const float* __restrict__ gamma,
                           const float* __restrict__ beta,
                           float* __restrict__ out) {
    int i = blockIdx.x * blockDim.x + threadIdx.x;
    if (i >= n) return;
    float4 nu = d_num2[i];
    float4 de = d_den2[i];
    float c = centrality[i];
    float s = 0.f, r;
    r = de.x > 0.f ? nu.x / de.x : 0.f; r = r > 0.f ? r : 0.f;
    s += (c * __ldg(&gamma[0]) + __ldg(&beta[0])) * r;
    r = de.y > 0.f ? nu.y / de.y : 0.f; r = r > 0.f ? r : 0.f;
    s += (c * __ldg(&gamma[1]) + __ldg(&beta[1])) * r;
    r = de.z > 0.f ? nu.z / de.z : 0.f; r = r > 0.f ? r : 0.f;
    s += (c * __ldg(&gamma[2]) + __ldg(&beta[2])) * r;
    r = de.w > 0.f ? nu.w / de.w : 0.f; r = r > 0.f ? r : 0.f;
    s += (c * __ldg(&gamma[3]) + __ldg(&beta[3])) * r;
    float v = 0.25f * s;
    out[i] = (v > 0.f) ? v : 0.01f * v;
}

// ---------------- launch -------------------------------------------------------
extern "C" void kernel_launch(void* const* d_in, const int* in_sizes, int n_in,
                              void* d_out, int out_size) {
    const float* inputs     = (const float*)d_in[0];
    const float* centrality = (const float*)d_in[1];
    const float* W1         = (const float*)d_in[2];
    const float* b1         = (const float*)d_in[3];
    const float* W2         = (const float*)d_in[4];
    const float* b2         = (const float*)d_in[5];
    const float* rel_emb    = (const float*)d_in[6];
    const float* W_pred     = (const float*)d_in[7];
    const float* gamma      = (const float*)d_in[8];
    const float* beta       = (const float*)d_in[9];
    const int*   et         = (const int*)d_in[10];
    const int*   src        = (const int*)d_in[11];
    const int*   dst        = (const int*)d_in[12];

    const int n = in_sizes[1];          // N
    const int e = in_sizes[10];         // E
    float* out = (float*)d_out;

    const int EB = (e + 255) / 256;
    const int NB = (n + 255) / 256;
    const int mlp_blocks = 2 * ((n + 127) / 128);

    k_init<<<2048, 256>>>(rel_emb, W_pred, n);

    // fat A: MLP (tensor) || histogram (L2 atomics) || num zeroing (DRAM)
    k_fatA<<<mlp_blocks + HIST_BLOCKS + ZERO_BLOCKS, 256>>>(
        inputs, W1, b1, W2, b2, et, dst, n, e, mlp_blocks);

    // fat B: layer-0 numerator REDs || den0/1/2 computation
    k_fatB<<<EB + NB, 256>>>(et, src, dst, e, n, EB);
    k_h1s<<<NB, 256>>>(n);

    // layer 1
    k_edgeS<0><<<EB, 256>>>(et, src, dst, e);
    k_combine1<<<NB, 256>>>(n);

    // layer 2 + epilogue
    k_edgeS<1><<<EB, 256>>>(et, src, dst, e);
    k_combine2<<<NB, 256>>>(n, centrality, gamma, beta, out);
}